// round 1
// baseline (speedup 1.0000x reference)
#include <cuda_runtime.h>

// Problem constants (fixed by setup_inputs)
#define E_EDGES 65536
#define D_DIM   200
#define H_DIM   100
#define T_TYPES 8
#define BK      8
#define BNP     112      // 16 col-threads * 7, padded (cols >= 100 are zero)
#define NEG_INF_F (-1e30f)

// CTA: 64 edge-pairs. 256 threads as 16x16; phase S: thread tile 4x7 over 64x100;
// phase D: thread tile 8x7 over 128x100 (rows 0..63 = pos dst, 64..127 = neg dst).
__global__ __launch_bounds__(256, 2)
void hetero_sthn_fused(const float* __restrict__ h,
                       const float* __restrict__ src_W, const float* __restrict__ src_b,
                       const float* __restrict__ dst_W, const float* __restrict__ dst_b,
                       const float* __restrict__ out_W, const float* __restrict__ out_b,
                       const int*   __restrict__ poss,
                       float* __restrict__ out)
{
    __shared__ float As[BK][128];        // A tile (src phase uses rows 0..63)
    __shared__ float Bs[BK][BNP];        // W tile, zero-padded cols
    __shared__ float Ssrc[64][BNP];      // src_enc tile (+src_b) for current t

    const int tid = threadIdx.x;
    const int tx  = tid & 15;            // column group 0..15
    const int ty  = tid >> 4;            // row group 0..15
    const int n0  = blockIdx.x * 64;     // first edge-pair index

    float best[8];
    int   anyv[8];
#pragma unroll
    for (int i = 0; i < 8; i++) { best[i] = NEG_INF_F; anyv[i] = 0; }

    for (int t = 0; t < T_TYPES; t++) {
        // ================= Phase S: src_enc tile (64 x 100) =================
        float accS[4][7];
#pragma unroll
        for (int i = 0; i < 4; i++)
#pragma unroll
            for (int j = 0; j < 7; j++) accS[i][j] = 0.0f;

        const float* Wt = src_W + (size_t)t * D_DIM * H_DIM;

        for (int k0 = 0; k0 < D_DIM; k0 += BK) {
            // Load A: 64 rows x 8 k, one float2 per thread
            {
                int row = tid >> 2;
                int kk  = (tid & 3) * 2;
                const float2 v = *(const float2*)(h + (size_t)(n0 + row) * D_DIM + k0 + kk);
                As[kk][row]     = v.x;
                As[kk + 1][row] = v.y;
            }
            // Load B: 8 x 112 (zero pad beyond col 100)
            for (int e = tid; e < BK * BNP; e += 256) {
                int kk = e / BNP, c = e - kk * BNP;
                Bs[kk][c] = (c < H_DIM) ? Wt[(size_t)(k0 + kk) * H_DIM + c] : 0.0f;
            }
            __syncthreads();
#pragma unroll
            for (int kk = 0; kk < BK; kk++) {
                float a[4], b[7];
#pragma unroll
                for (int i = 0; i < 4; i++) a[i] = As[kk][ty * 4 + i];
#pragma unroll
                for (int j = 0; j < 7; j++) b[j] = Bs[kk][tx * 7 + j];
#pragma unroll
                for (int i = 0; i < 4; i++)
#pragma unroll
                    for (int j = 0; j < 7; j++)
                        accS[i][j] = fmaf(a[i], b[j], accS[i][j]);
            }
            __syncthreads();
        }
        // Stage src_enc (+ src_b) into smem for the epilogue
#pragma unroll
        for (int i = 0; i < 4; i++)
#pragma unroll
            for (int j = 0; j < 7; j++) {
                int c = tx * 7 + j;
                float bias = (c < H_DIM) ? src_b[t * H_DIM + c] : 0.0f;
                Ssrc[ty * 4 + i][c] = accS[i][j] + bias;
            }

        // ================= Phase D: dst_enc tile (128 x 100) =================
        float accD[8][7];
#pragma unroll
        for (int i = 0; i < 8; i++)
#pragma unroll
            for (int j = 0; j < 7; j++) accD[i][j] = 0.0f;

        const float* Wd = dst_W + (size_t)t * D_DIM * H_DIM;

        for (int k0 = 0; k0 < D_DIM; k0 += BK) {
            // Load A: 128 rows x 8 k, two float2 per thread
#pragma unroll
            for (int s = 0; s < 2; s++) {
                int e   = tid + s * 256;
                int row = e >> 2;
                int kk  = (e & 3) * 2;
                size_t grow = (row < 64) ? (size_t)(E_EDGES + n0 + row)
                                         : (size_t)(2 * E_EDGES + n0 + row - 64);
                const float2 v = *(const float2*)(h + grow * D_DIM + k0 + kk);
                As[kk][row]     = v.x;
                As[kk + 1][row] = v.y;
            }
            for (int e = tid; e < BK * BNP; e += 256) {
                int kk = e / BNP, c = e - kk * BNP;
                Bs[kk][c] = (c < H_DIM) ? Wd[(size_t)(k0 + kk) * H_DIM + c] : 0.0f;
            }
            __syncthreads();
#pragma unroll
            for (int kk = 0; kk < BK; kk++) {
                float a[8], b[7];
#pragma unroll
                for (int i = 0; i < 8; i++) a[i] = As[kk][ty * 8 + i];
#pragma unroll
                for (int j = 0; j < 7; j++) b[j] = Bs[kk][tx * 7 + j];
#pragma unroll
                for (int i = 0; i < 8; i++)
#pragma unroll
                    for (int j = 0; j < 7; j++)
                        accD[i][j] = fmaf(a[i], b[j], accD[i][j]);
            }
            __syncthreads();
        }

        // ================= Epilogue: relu, out-dot, masked max =================
#pragma unroll
        for (int i = 0; i < 8; i++) {
            int r = ty * 8 + i;              // 0..127 within dst tile
            float p = 0.0f;
#pragma unroll
            for (int j = 0; j < 7; j++) {
                int c = tx * 7 + j;
                if (c < H_DIM) {
                    float v = accD[i][j] + dst_b[t * H_DIM + c] + Ssrc[r & 63][c];
                    v = fmaxf(v, 0.0f);
                    p = fmaf(v, out_W[t * H_DIM + c], p);
                }
            }
            // reduce across the 16 column threads (half-warp)
#pragma unroll
            for (int off = 8; off > 0; off >>= 1)
                p += __shfl_xor_sync(0xffffffffu, p, off, 16);

            if (tx == 0) {
                int edge = (r < 64) ? (n0 + r) : (E_EDGES + n0 + r - 64);
                if (poss[(size_t)edge * T_TYPES + t] != 0) {
                    float pred = p + out_b[t];
                    best[i] = fmaxf(best[i], pred);
                    anyv[i] = 1;
                }
            }
        }
        __syncthreads();   // protect Ssrc/As/Bs reuse next t
    }

    if (tx == 0) {
#pragma unroll
        for (int i = 0; i < 8; i++) {
            int r = ty * 8 + i;
            int edge = (r < 64) ? (n0 + r) : (E_EDGES + n0 + r - 64);
            out[edge] = anyv[i] ? best[i] : 0.0f;
        }
    }
}

extern "C" void kernel_launch(void* const* d_in, const int* in_sizes, int n_in,
                              void* d_out, int out_size)
{
    const float* h      = (const float*)d_in[0];
    const float* src_W  = (const float*)d_in[1];
    const float* src_b  = (const float*)d_in[2];
    const float* dst_W  = (const float*)d_in[3];
    const float* dst_b  = (const float*)d_in[4];
    const float* out_W  = (const float*)d_in[5];
    const float* out_b  = (const float*)d_in[6];
    const int*   poss   = (const int*)d_in[7];
    float*       out    = (float*)d_out;

    dim3 grid(E_EDGES / 64);   // 1024 CTAs, each handles 64 pos + 64 neg edges
    dim3 block(256);
    hetero_sthn_fused<<<grid, block>>>(h, src_W, src_b, dst_W, dst_b,
                                       out_W, out_b, poss, out);
}

// round 3
// speedup vs baseline: 10.7547x; 10.7547x over previous
#include <cuda_runtime.h>
#include <cuda_fp16.h>
#include <cstdint>

// ---------------- problem constants ----------------
#define E_EDGES 65536
#define D_K     200
#define H_N     100
#define T_TYPES 8
#define P_PAIRS 64                      // edge-pairs per CTA
#define NCTA    (E_EDGES / P_PAIRS)     // 1024
#define KP      208                     // K padded (13 x k16)
#define NP      104                     // N padded (13 x n8)
#define AROWB   432                     // A row stride bytes (216 halves) - LDSM conflict-free
#define BROWB   208                     // B row stride bytes (104 halves) - LDSM conflict-free
#define A_SZ    (P_PAIRS * AROWB)       // 27648
#define B_SZ    (KP * BROWB)            // 43264

// smem offsets
#define OFF_AS  0
#define OFF_AP  (A_SZ)
#define OFF_AN  (2 * A_SZ)
#define OFF_BS  (3 * A_SZ)              // 82944
#define OFF_BD  (OFF_BS + B_SZ)         // 126208
#define OFF_CB  (OFF_BD + B_SZ)         // 169472  (104 f32: src_b+dst_b)
#define OFF_OW  (OFF_CB + NP * 4)       // 169888  (104 f32: out_W)
#define OFF_EP  (OFF_OW + NP * 4)       // 170304  (2*64 f32)
#define OFF_EN  (OFF_EP + 128 * 4)      // 170816
#define SMEM_TOTAL (OFF_EN + 128 * 4)   // 171328

// preconverted weights: [mat(2)][t(8)][k(208)][n(104)] fp16, pads zero
__device__ __align__(16) __half g_W16[2 * T_TYPES * KP * NP];

// ---------------- helpers ----------------
__device__ __forceinline__ uint32_t smem_u32(const void* p) {
    uint32_t a;
    asm("{ .reg .u64 t; cvta.to.shared.u64 t, %1; cvt.u32.u64 %0, t; }" : "=r"(a) : "l"(p));
    return a;
}
__device__ __forceinline__ void ldsm_x4(uint32_t* r, uint32_t a) {
    asm volatile("ldmatrix.sync.aligned.m8n8.x4.shared.b16 {%0,%1,%2,%3}, [%4];"
        : "=r"(r[0]), "=r"(r[1]), "=r"(r[2]), "=r"(r[3]) : "r"(a));
}
__device__ __forceinline__ void ldsm_x4t(uint32_t* r, uint32_t a) {
    asm volatile("ldmatrix.sync.aligned.m8n8.x4.trans.shared.b16 {%0,%1,%2,%3}, [%4];"
        : "=r"(r[0]), "=r"(r[1]), "=r"(r[2]), "=r"(r[3]) : "r"(a));
}
__device__ __forceinline__ void ldsm_x2t(uint32_t* r, uint32_t a) {
    asm volatile("ldmatrix.sync.aligned.m8n8.x2.trans.shared.b16 {%0,%1}, [%2];"
        : "=r"(r[0]), "=r"(r[1]) : "r"(a));
}
__device__ __forceinline__ void mma16816(float* c, const uint32_t* a, const uint32_t* b) {
    asm volatile("mma.sync.aligned.m16n8k16.row.col.f32.f16.f16.f32 "
        "{%0,%1,%2,%3}, {%4,%5,%6,%7}, {%8,%9}, {%0,%1,%2,%3};"
        : "+f"(c[0]), "+f"(c[1]), "+f"(c[2]), "+f"(c[3])
        : "r"(a[0]), "r"(a[1]), "r"(a[2]), "r"(a[3]), "r"(b[0]), "r"(b[1]));
}
__device__ __forceinline__ uint32_t pack_h2(float x, float y) {
    __half2 t = __floats2half2_rn(x, y);
    return *reinterpret_cast<uint32_t*>(&t);
}

// ---------------- prologue: weights -> fp16 [mat][t][k][n], zero-padded ----------------
__global__ void wconv_kernel(const float* __restrict__ srcW, const float* __restrict__ dstW) {
    int i = blockIdx.x * blockDim.x + threadIdx.x;
    const int TOT = 2 * T_TYPES * KP * NP;
    if (i >= TOT) return;
    int n   = i % NP;
    int k   = (i / NP) % KP;
    int t   = (i / (NP * KP)) % T_TYPES;
    int mat = i / (NP * KP * T_TYPES);
    float v = 0.0f;
    if (k < D_K && n < H_N) {
        const float* W = mat ? dstW : srcW;
        v = W[(size_t)t * D_K * H_N + (size_t)k * H_N + n];
    }
    g_W16[i] = __float2half_rn(v);
}

// ---------------- the fused k-loop (NBLK = 7 for n-half 0, 6 for n-half 1) ----------------
template <int NBLK>
__device__ __forceinline__ void run_kloop(
    uint32_t aS, uint32_t aP, uint32_t aN,
    uint32_t bs0, uint32_t bs1, uint32_t bs2, uint32_t bs6,
    uint32_t bd0, uint32_t bd1, uint32_t bd2, uint32_t bd6,
    float (&cS)[7][4], float (&cP)[7][4], float (&cN)[7][4])
{
#pragma unroll
    for (int s = 0; s < 13; s++) {
        const uint32_t ka = s * 32;              // 16 halves per k-step
        const uint32_t kb = s * 16 * BROWB;      // 16 B-rows per k-step
        uint32_t a0[4], a1[4], a2[4];
        ldsm_x4(a0, aS + ka);
        ldsm_x4(a1, aP + ka);
        ldsm_x4(a2, aN + ka);
        uint32_t bs[14], bd[14];
        ldsm_x4t(bs + 0, bs0 + kb);
        ldsm_x4t(bs + 4, bs1 + kb);
        ldsm_x4t(bs + 8, bs2 + kb);
        ldsm_x4t(bd + 0, bd0 + kb);
        ldsm_x4t(bd + 4, bd1 + kb);
        ldsm_x4t(bd + 8, bd2 + kb);
        if (NBLK == 7) {
            ldsm_x2t(bs + 12, bs6 + kb);
            ldsm_x2t(bd + 12, bd6 + kb);
        }
#pragma unroll
        for (int j = 0; j < NBLK; j++) {
            mma16816(cS[j], a0, bs + 2 * j);
            mma16816(cP[j], a1, bd + 2 * j);
            mma16816(cN[j], a2, bd + 2 * j);
        }
    }
}

// ---------------- main fused kernel ----------------
__global__ __launch_bounds__(256, 1)
void sthn_hmma_kernel(const float* __restrict__ h,
                      const float* __restrict__ src_b, const float* __restrict__ dst_b,
                      const float* __restrict__ out_W, const float* __restrict__ out_b,
                      const int*   __restrict__ poss,
                      float* __restrict__ out)
{
    extern __shared__ char smem[];
    const uint32_t sb = smem_u32(smem);
    const int tid  = threadIdx.x;
    const int lane = tid & 31;
    const int w    = tid >> 5;
    const int n0   = blockIdx.x * P_PAIRS;

    // ---- convert the three A tiles fp32 -> fp16 into smem (once) ----
    {
        const int QUADS = AROWB / 8;   // 54 uint2-stores (4 halves) per row
        for (int idx = tid; idx < 3 * P_PAIRS * QUADS; idx += 256) {
            int tile = idx / (P_PAIRS * QUADS);
            int rem  = idx - tile * (P_PAIRS * QUADS);
            int row  = rem / QUADS;
            int kq   = rem - row * QUADS;
            int k    = kq * 4;
            uint2 v16;
            if (k < D_K) {
                const float4 v = *reinterpret_cast<const float4*>(
                    h + (size_t)(tile * E_EDGES + n0 + row) * D_K + k);
                v16.x = pack_h2(v.x, v.y);
                v16.y = pack_h2(v.z, v.w);
            } else { v16.x = 0u; v16.y = 0u; }
            *reinterpret_cast<uint2*>(smem + tile * A_SZ + row * AROWB + k * 2) = v16;
        }
    }

    // ---- per-warp fragment addressing (constant across t) ----
    const int mb    = (w & 3) * 16;     // M block base row
    const int nh    = w >> 2;           // n-half: 0 -> blocks 0..6, 1 -> blocks 7..12
    const int nbase = nh * 7;
    const int nblk  = nh ? 6 : 7;

    const uint32_t aOff = (uint32_t)(mb + (lane & 15)) * AROWB + (uint32_t)(lane >> 4) * 16;
    const uint32_t aS = sb + OFF_AS + aOff;
    const uint32_t aP = sb + OFF_AP + aOff;
    const uint32_t aN = sb + OFF_AN + aOff;

    const uint32_t bRow = (uint32_t)(lane & 15) * BROWB;
    const uint32_t bSel = (uint32_t)(lane >> 4);
    const uint32_t b0o = bRow + (nbase + 0 + bSel) * 16;
    const uint32_t b1o = bRow + (nbase + 2 + bSel) * 16;
    const uint32_t b2o = bRow + (nbase + 4 + bSel) * 16;
    const uint32_t b6o = bRow + (nbase + 6) * 16;
    const uint32_t bs0 = sb + OFF_BS + b0o, bd0 = sb + OFF_BD + b0o;
    const uint32_t bs1 = sb + OFF_BS + b1o, bd1 = sb + OFF_BD + b1o;
    const uint32_t bs2 = sb + OFF_BS + b2o, bd2 = sb + OFF_BD + b2o;
    const uint32_t bs6 = sb + OFF_BS + b6o, bd6 = sb + OFF_BD + b6o;

    float* EP = reinterpret_cast<float*>(smem + OFF_EP);
    float* EN = reinterpret_cast<float*>(smem + OFF_EN);
    const float* CB = reinterpret_cast<const float*>(smem + OFF_CB);
    const float* OW = reinterpret_cast<const float*>(smem + OFF_OW);

    float bestP = -1e30f, bestN = -1e30f;
    int   anyP = 0, anyN = 0;

    for (int t = 0; t < T_TYPES; t++) {
        // ---- stage both weight tiles (straight copy, layout identical) ----
        {
            const uint4* gs = reinterpret_cast<const uint4*>(g_W16 + (size_t)t * KP * NP);
            const uint4* gd = reinterpret_cast<const uint4*>(g_W16 + (size_t)(T_TYPES + t) * KP * NP);
            uint4* ds = reinterpret_cast<uint4*>(smem + OFF_BS);
            uint4* dd = reinterpret_cast<uint4*>(smem + OFF_BD);
            for (int i = tid; i < B_SZ / 16; i += 256) { ds[i] = gs[i]; dd[i] = gd[i]; }
        }
        if (tid < NP) {
            int c = tid;
            float cb = 0.0f, ow = 0.0f;
            if (c < H_N) {
                cb = src_b[t * H_N + c] + dst_b[t * H_N + c];
                ow = out_W[t * H_N + c];
            }
            reinterpret_cast<float*>(smem + OFF_CB)[c] = cb;
            reinterpret_cast<float*>(smem + OFF_OW)[c] = ow;
        }
        __syncthreads();

        // ---- the three fused GEMMs over K ----
        float cS[7][4], cP[7][4], cN[7][4];
#pragma unroll
        for (int j = 0; j < 7; j++)
#pragma unroll
            for (int q = 0; q < 4; q++) { cS[j][q] = 0.f; cP[j][q] = 0.f; cN[j][q] = 0.f; }

        if (nh == 0)
            run_kloop<7>(aS, aP, aN, bs0, bs1, bs2, bs6, bd0, bd1, bd2, bd6, cS, cP, cN);
        else
            run_kloop<6>(aS, aP, aN, bs0, bs1, bs2, bs6, bd0, bd1, bd2, bd6, cS, cP, cN);

        // ---- epilogue: relu-combine + out_W dot, per-thread then quad-reduce ----
        float pP0 = 0.f, pP1 = 0.f, pN0 = 0.f, pN1 = 0.f;
        for (int j = 0; j < nblk; j++) {
            const int c0 = (nbase + j) * 8 + (lane & 3) * 2;
            const float cb0 = CB[c0], cb1 = CB[c0 + 1];
            const float ow0 = OW[c0], ow1 = OW[c0 + 1];
            pP0 += fmaxf(cS[j][0] + cP[j][0] + cb0, 0.f) * ow0
                 + fmaxf(cS[j][1] + cP[j][1] + cb1, 0.f) * ow1;
            pP1 += fmaxf(cS[j][2] + cP[j][2] + cb0, 0.f) * ow0
                 + fmaxf(cS[j][3] + cP[j][3] + cb1, 0.f) * ow1;
            pN0 += fmaxf(cS[j][0] + cN[j][0] + cb0, 0.f) * ow0
                 + fmaxf(cS[j][1] + cN[j][1] + cb1, 0.f) * ow1;
            pN1 += fmaxf(cS[j][2] + cN[j][2] + cb0, 0.f) * ow0
                 + fmaxf(cS[j][3] + cN[j][3] + cb1, 0.f) * ow1;
        }
#pragma unroll
        for (int off = 1; off <= 2; off <<= 1) {
            pP0 += __shfl_xor_sync(0xffffffffu, pP0, off);
            pP1 += __shfl_xor_sync(0xffffffffu, pP1, off);
            pN0 += __shfl_xor_sync(0xffffffffu, pN0, off);
            pN1 += __shfl_xor_sync(0xffffffffu, pN1, off);
        }
        if ((lane & 3) == 0) {
            const int r0 = mb + (lane >> 2);
            EP[nh * 64 + r0] = pP0;  EP[nh * 64 + r0 + 8] = pP1;
            EN[nh * 64 + r0] = pN0;  EN[nh * 64 + r0 + 8] = pN1;
        }
        __syncthreads();

        if (tid < P_PAIRS) {
            const float ob = out_b[t];
            const float sp = EP[tid] + EP[64 + tid] + ob;
            const float sn = EN[tid] + EN[64 + tid] + ob;
            if (poss[(size_t)(n0 + tid) * T_TYPES + t] != 0)           { bestP = fmaxf(bestP, sp); anyP = 1; }
            if (poss[(size_t)(E_EDGES + n0 + tid) * T_TYPES + t] != 0) { bestN = fmaxf(bestN, sn); anyN = 1; }
        }
        __syncthreads();   // EP/EN + B buffers reused next t
    }

    if (tid < P_PAIRS) {
        out[n0 + tid]           = anyP ? bestP : 0.0f;
        out[E_EDGES + n0 + tid] = anyN ? bestN : 0.0f;
    }
}

// ---------------- launch ----------------
extern "C" void kernel_launch(void* const* d_in, const int* in_sizes, int n_in,
                              void* d_out, int out_size)
{
    const float* h      = (const float*)d_in[0];
    const float* src_W  = (const float*)d_in[1];
    const float* src_b  = (const float*)d_in[2];
    const float* dst_W  = (const float*)d_in[3];
    const float* dst_b  = (const float*)d_in[4];
    const float* out_W  = (const float*)d_in[5];
    const float* out_b  = (const float*)d_in[6];
    const int*   poss   = (const int*)d_in[7];
    float*       out    = (float*)d_out;

    cudaFuncSetAttribute(sthn_hmma_kernel,
                         cudaFuncAttributeMaxDynamicSharedMemorySize, SMEM_TOTAL);

    const int wtot = 2 * T_TYPES * KP * NP;
    wconv_kernel<<<(wtot + 255) / 256, 256>>>(src_W, dst_W);
    sthn_hmma_kernel<<<NCTA, 256, SMEM_TOTAL>>>(h, src_b, dst_b, out_W, out_b, poss, out);
}

// round 4
// speedup vs baseline: 11.1978x; 1.0412x over previous
#include <cuda_runtime.h>
#include <cuda_fp16.h>
#include <cstdint>

// ---------------- problem constants ----------------
#define E_EDGES 65536
#define D_K     200
#define H_N     100
#define T_TYPES 8
#define P_PAIRS 128                     // edge-pairs per CTA
#define NCTA    (E_EDGES / P_PAIRS)     // 512
#define KP      208                     // K padded (13 x k16)
#define NP      104                     // N padded (13 x n8)
#define AROWB   432                     // A row stride bytes (216 halves), LDSM conflict-free
#define BROWB   208                     // B row stride bytes (104 halves), LDSM conflict-free
#define A_SZ    (P_PAIRS * AROWB)       // 55296
#define B_SZ    (KP * BROWB)            // 43264

// smem offsets
#define OFF_AS  0
#define OFF_AP  (A_SZ)
#define OFF_AN  (2 * A_SZ)
#define OFF_B   (3 * A_SZ)              // 165888
#define OFF_CB  (OFF_B + B_SZ)          // 209152 (104 f32: src_b+dst_b)
#define OFF_OW  (OFF_CB + NP * 4)       // 209568 (104 f32: out_W)
#define OFF_EP  (OFF_OW + NP * 4)       // 209984 (2*128 f32)
#define OFF_EN  (OFF_EP + 256 * 4)      // 211008 (2*128 f32)
#define SMEM_TOTAL (OFF_EN + 256 * 4)   // 212032

// preconverted weights: [mat(2)][t(8)][k(208)][n(104)] fp16, pads zero
__device__ __align__(16) __half g_W16[2 * T_TYPES * KP * NP];

// ---------------- helpers ----------------
__device__ __forceinline__ uint32_t smem_u32(const void* p) {
    uint32_t a;
    asm("{ .reg .u64 t; cvta.to.shared.u64 t, %1; cvt.u32.u64 %0, t; }" : "=r"(a) : "l"(p));
    return a;
}
__device__ __forceinline__ void ldsm_x4(uint32_t* r, uint32_t a) {
    asm volatile("ldmatrix.sync.aligned.m8n8.x4.shared.b16 {%0,%1,%2,%3}, [%4];"
        : "=r"(r[0]), "=r"(r[1]), "=r"(r[2]), "=r"(r[3]) : "r"(a));
}
__device__ __forceinline__ void ldsm_x4t(uint32_t* r, uint32_t a) {
    asm volatile("ldmatrix.sync.aligned.m8n8.x4.trans.shared.b16 {%0,%1,%2,%3}, [%4];"
        : "=r"(r[0]), "=r"(r[1]), "=r"(r[2]), "=r"(r[3]) : "r"(a));
}
__device__ __forceinline__ void ldsm_x2t(uint32_t* r, uint32_t a) {
    asm volatile("ldmatrix.sync.aligned.m8n8.x2.trans.shared.b16 {%0,%1}, [%2];"
        : "=r"(r[0]), "=r"(r[1]) : "r"(a));
}
__device__ __forceinline__ void mma16816(float* c, const uint32_t* a, const uint32_t* b) {
    asm volatile("mma.sync.aligned.m16n8k16.row.col.f32.f16.f16.f32 "
        "{%0,%1,%2,%3}, {%4,%5,%6,%7}, {%8,%9}, {%0,%1,%2,%3};"
        : "+f"(c[0]), "+f"(c[1]), "+f"(c[2]), "+f"(c[3])
        : "r"(a[0]), "r"(a[1]), "r"(a[2]), "r"(a[3]), "r"(b[0]), "r"(b[1]));
}
__device__ __forceinline__ uint32_t pack_h2(float x, float y) {
    __half2 t = __floats2half2_rn(x, y);
    return *reinterpret_cast<uint32_t*>(&t);
}

// ---------------- prologue: weights -> fp16 [mat][t][k][n], zero-padded ----------------
__global__ void wconv_kernel(const float* __restrict__ srcW, const float* __restrict__ dstW) {
    int i = blockIdx.x * blockDim.x + threadIdx.x;
    const int TOT = 2 * T_TYPES * KP * NP;
    if (i >= TOT) return;
    int n   = i % NP;
    int k   = (i / NP) % KP;
    int t   = (i / (NP * KP)) % T_TYPES;
    int mat = i / (NP * KP * T_TYPES);
    float v = 0.0f;
    if (k < D_K && n < H_N) {
        const float* W = mat ? dstW : srcW;
        v = W[(size_t)t * D_K * H_N + (size_t)k * H_N + n];
    }
    g_W16[i] = __float2half_rn(v);
}

// ---------------- k-loops ----------------
// phase 1: c[r][j] += A_src(rows mb+16r) @ Ws(block nbase+j)
template <int NBLK>
__device__ __forceinline__ void kloop_src(
    uint32_t a0, uint32_t a1,
    uint32_t b0, uint32_t b1, uint32_t b2, uint32_t b6,
    float (&c)[2][7][4])
{
#pragma unroll
    for (int s = 0; s < 13; s++) {
        const uint32_t ka = s * 32;
        const uint32_t kb = s * 16 * BROWB;
        uint32_t A0[4], A1[4];
        ldsm_x4(A0, a0 + ka);
        ldsm_x4(A1, a1 + ka);
        uint32_t B[14];
        ldsm_x4t(B + 0, b0 + kb);
        ldsm_x4t(B + 4, b1 + kb);
        ldsm_x4t(B + 8, b2 + kb);
        if (NBLK == 7) ldsm_x2t(B + 12, b6 + kb);
#pragma unroll
        for (int j = 0; j < NBLK; j++) {
            mma16816(c[0][j], A0, B + 2 * j);
            mma16816(c[1][j], A1, B + 2 * j);
        }
    }
}

// phase 2: cP[r][j] += A_pos @ Wd ; cN[r][j] += A_neg @ Wd
template <int NBLK>
__device__ __forceinline__ void kloop_dst(
    uint32_t p0, uint32_t p1, uint32_t q0, uint32_t q1,
    uint32_t b0, uint32_t b1, uint32_t b2, uint32_t b6,
    float (&cP)[2][7][4], float (&cN)[2][7][4])
{
#pragma unroll
    for (int s = 0; s < 13; s++) {
        const uint32_t ka = s * 32;
        const uint32_t kb = s * 16 * BROWB;
        uint32_t P0[4], P1[4], Q0[4], Q1[4];
        ldsm_x4(P0, p0 + ka);
        ldsm_x4(P1, p1 + ka);
        ldsm_x4(Q0, q0 + ka);
        ldsm_x4(Q1, q1 + ka);
        uint32_t B[14];
        ldsm_x4t(B + 0, b0 + kb);
        ldsm_x4t(B + 4, b1 + kb);
        ldsm_x4t(B + 8, b2 + kb);
        if (NBLK == 7) ldsm_x2t(B + 12, b6 + kb);
#pragma unroll
        for (int j = 0; j < NBLK; j++) {
            mma16816(cP[0][j], P0, B + 2 * j);
            mma16816(cP[1][j], P1, B + 2 * j);
            mma16816(cN[0][j], Q0, B + 2 * j);
            mma16816(cN[1][j], Q1, B + 2 * j);
        }
    }
}

// ---------------- main fused kernel ----------------
__global__ __launch_bounds__(256, 1)
void sthn_hmma_kernel(const float* __restrict__ h,
                      const float* __restrict__ src_b, const float* __restrict__ dst_b,
                      const float* __restrict__ out_W, const float* __restrict__ out_b,
                      const int*   __restrict__ poss,
                      float* __restrict__ out)
{
    extern __shared__ char smem[];
    const uint32_t sb = smem_u32(smem);
    const int tid  = threadIdx.x;
    const int lane = tid & 31;
    const int w    = tid >> 5;
    const int n0   = blockIdx.x * P_PAIRS;

    // ---- convert the three A tiles fp32 -> fp16 into smem (once) ----
    {
        const int QUADS = KP / 4;   // 52 uint2-stores (4 halves each) per row
        for (int idx = tid; idx < 3 * P_PAIRS * QUADS; idx += 256) {
            int tile = idx / (P_PAIRS * QUADS);
            int rem  = idx - tile * (P_PAIRS * QUADS);
            int row  = rem / QUADS;
            int k    = (rem - row * QUADS) * 4;
            uint2 v16;
            if (k < D_K) {
                const float4 v = *reinterpret_cast<const float4*>(
                    h + (size_t)(tile * E_EDGES + n0 + row) * D_K + k);
                v16.x = pack_h2(v.x, v.y);
                v16.y = pack_h2(v.z, v.w);
            } else { v16.x = 0u; v16.y = 0u; }
            *reinterpret_cast<uint2*>(smem + tile * A_SZ + row * AROWB + k * 2) = v16;
        }
    }

    // ---- per-warp fragment addressing (constant across t) ----
    const int mb    = (w & 3) * 32;     // 32 M rows per warp
    const int nh    = w >> 2;           // n-half
    const int nbase = nh * 7;
    const int nblk  = nh ? 6 : 7;

    const uint32_t aOff0 = (uint32_t)(mb + (lane & 15)) * AROWB + (uint32_t)(lane >> 4) * 16;
    const uint32_t aOff1 = aOff0 + 16u * AROWB;
    const uint32_t aS0 = sb + OFF_AS + aOff0, aS1 = sb + OFF_AS + aOff1;
    const uint32_t aP0 = sb + OFF_AP + aOff0, aP1 = sb + OFF_AP + aOff1;
    const uint32_t aN0 = sb + OFF_AN + aOff0, aN1 = sb + OFF_AN + aOff1;

    const uint32_t bRow = (uint32_t)(lane & 15) * BROWB;
    const uint32_t bSel = (uint32_t)(lane >> 4);
    const uint32_t b0 = sb + OFF_B + bRow + (nbase + 0 + bSel) * 16;
    const uint32_t b1 = sb + OFF_B + bRow + (nbase + 2 + bSel) * 16;
    const uint32_t b2 = sb + OFF_B + bRow + (nbase + 4 + bSel) * 16;
    const uint32_t b6 = sb + OFF_B + bRow + (nbase + 6) * 16;

    float* EP = reinterpret_cast<float*>(smem + OFF_EP);
    float* EN = reinterpret_cast<float*>(smem + OFF_EN);
    const float* CB = reinterpret_cast<const float*>(smem + OFF_CB);
    const float* OW = reinterpret_cast<const float*>(smem + OFF_OW);

    float bestP = -1e30f, bestN = -1e30f;
    int   anyP = 0, anyN = 0;

    for (int t = 0; t < T_TYPES; t++) {
        // ---- stage Ws(t) into the single B buffer + epilogue constants ----
        {
            const uint4* gs = reinterpret_cast<const uint4*>(g_W16 + (size_t)t * KP * NP);
            uint4* db = reinterpret_cast<uint4*>(smem + OFF_B);
            for (int i = tid; i < B_SZ / 16; i += 256) db[i] = gs[i];
        }
        if (tid < NP) {
            int c = tid;
            float cb = 0.0f, ow = 0.0f;
            if (c < H_N) {
                cb = src_b[t * H_N + c] + dst_b[t * H_N + c];
                ow = out_W[t * H_N + c];
            }
            reinterpret_cast<float*>(smem + OFF_CB)[c] = cb;
            reinterpret_cast<float*>(smem + OFF_OW)[c] = ow;
        }
        __syncthreads();

        // ---- phase 1: cP = A_src @ Ws ----
        float cP[2][7][4], cN[2][7][4];
#pragma unroll
        for (int r = 0; r < 2; r++)
#pragma unroll
            for (int j = 0; j < 7; j++)
#pragma unroll
                for (int q = 0; q < 4; q++) cP[r][j][q] = 0.f;

        if (nh == 0) kloop_src<7>(aS0, aS1, b0, b1, b2, b6, cP);
        else         kloop_src<6>(aS0, aS1, b0, b1, b2, b6, cP);

        // src contribution is shared: copy into cN
#pragma unroll
        for (int r = 0; r < 2; r++)
#pragma unroll
            for (int j = 0; j < 7; j++)
#pragma unroll
                for (int q = 0; q < 4; q++) cN[r][j][q] = cP[r][j][q];

        __syncthreads();   // all warps done reading Ws

        // ---- stage Wd(t) ----
        {
            const uint4* gd = reinterpret_cast<const uint4*>(g_W16 + (size_t)(T_TYPES + t) * KP * NP);
            uint4* db = reinterpret_cast<uint4*>(smem + OFF_B);
            for (int i = tid; i < B_SZ / 16; i += 256) db[i] = gd[i];
        }
        __syncthreads();

        // ---- phase 2: cP += A_pos @ Wd ; cN += A_neg @ Wd ----
        if (nh == 0) kloop_dst<7>(aP0, aP1, aN0, aN1, b0, b1, b2, b6, cP, cN);
        else         kloop_dst<6>(aP0, aP1, aN0, aN1, b0, b1, b2, b6, cP, cN);

        // ---- epilogue: relu + out_W dot, quad-reduce, stage to smem ----
#pragma unroll
        for (int r = 0; r < 2; r++) {
            float pP0 = 0.f, pP1 = 0.f, pN0 = 0.f, pN1 = 0.f;
            for (int j = 0; j < nblk; j++) {
                const int c0 = (nbase + j) * 8 + (lane & 3) * 2;
                const float cb0 = CB[c0], cb1 = CB[c0 + 1];
                const float ow0 = OW[c0], ow1 = OW[c0 + 1];
                pP0 += fmaxf(cP[r][j][0] + cb0, 0.f) * ow0 + fmaxf(cP[r][j][1] + cb1, 0.f) * ow1;
                pP1 += fmaxf(cP[r][j][2] + cb0, 0.f) * ow0 + fmaxf(cP[r][j][3] + cb1, 0.f) * ow1;
                pN0 += fmaxf(cN[r][j][0] + cb0, 0.f) * ow0 + fmaxf(cN[r][j][1] + cb1, 0.f) * ow1;
                pN1 += fmaxf(cN[r][j][2] + cb0, 0.f) * ow0 + fmaxf(cN[r][j][3] + cb1, 0.f) * ow1;
            }
#pragma unroll
            for (int off = 1; off <= 2; off <<= 1) {
                pP0 += __shfl_xor_sync(0xffffffffu, pP0, off);
                pP1 += __shfl_xor_sync(0xffffffffu, pP1, off);
                pN0 += __shfl_xor_sync(0xffffffffu, pN0, off);
                pN1 += __shfl_xor_sync(0xffffffffu, pN1, off);
            }
            if ((lane & 3) == 0) {
                const int r0 = mb + 16 * r + (lane >> 2);
                EP[nh * P_PAIRS + r0] = pP0;  EP[nh * P_PAIRS + r0 + 8] = pP1;
                EN[nh * P_PAIRS + r0] = pN0;  EN[nh * P_PAIRS + r0 + 8] = pN1;
            }
        }
        __syncthreads();

        if (tid < P_PAIRS) {
            const float ob = out_b[t];
            const float sp = EP[tid] + EP[P_PAIRS + tid] + ob;
            const float sn = EN[tid] + EN[P_PAIRS + tid] + ob;
            if (poss[(size_t)(n0 + tid) * T_TYPES + t] != 0)           { bestP = fmaxf(bestP, sp); anyP = 1; }
            if (poss[(size_t)(E_EDGES + n0 + tid) * T_TYPES + t] != 0) { bestN = fmaxf(bestN, sn); anyN = 1; }
        }
        __syncthreads();   // EP/EN + B buffer reused next t
    }

    if (tid < P_PAIRS) {
        out[n0 + tid]           = anyP ? bestP : 0.0f;
        out[E_EDGES + n0 + tid] = anyN ? bestN : 0.0f;
    }
}

// ---------------- launch ----------------
extern "C" void kernel_launch(void* const* d_in, const int* in_sizes, int n_in,
                              void* d_out, int out_size)
{
    const float* h      = (const float*)d_in[0];
    const float* src_W  = (const float*)d_in[1];
    const float* src_b  = (const float*)d_in[2];
    const float* dst_W  = (const float*)d_in[3];
    const float* dst_b  = (const float*)d_in[4];
    const float* out_W  = (const float*)d_in[5];
    const float* out_b  = (const float*)d_in[6];
    const int*   poss   = (const int*)d_in[7];
    float*       out    = (float*)d_out;

    cudaFuncSetAttribute(sthn_hmma_kernel,
                         cudaFuncAttributeMaxDynamicSharedMemorySize, SMEM_TOTAL);

    const int wtot = 2 * T_TYPES * KP * NP;
    wconv_kernel<<<(wtot + 255) / 256, 256>>>(src_W, dst_W);
    sthn_hmma_kernel<<<NCTA, 256, SMEM_TOTAL>>>(h, src_b, dst_b, out_W, out_b, poss, out);
}

// round 5
// speedup vs baseline: 11.9856x; 1.0704x over previous
#include <cuda_runtime.h>
#include <cuda_fp16.h>
#include <cstdint>

// ---------------- problem constants ----------------
#define E_EDGES 65536
#define D_K     200
#define H_N     100
#define T_TYPES 8
#define P_PAIRS 128                     // edge-pairs per CTA
#define NCTA    (E_EDGES / P_PAIRS)     // 512
#define NTHREADS 384
#define KP      208                     // K padded (13 x k16)
#define NP      104                     // N padded (13 x n8)
#define AROWB   432                     // A row stride bytes, LDSM conflict-free
#define BROWB   208                     // B row stride bytes, LDSM conflict-free
#define A_SZ    (P_PAIRS * AROWB)       // 55296
#define BCH     23296                   // B chunk buffer (112 rows x 208 B)

// smem offsets
#define OFF_AS  0
#define OFF_AP  (A_SZ)
#define OFF_AN  (2 * A_SZ)
#define OFF_B0  (3 * A_SZ)              // 165888
#define OFF_B1  (OFF_B0 + BCH)          // 189184
#define OFF_CB  (OFF_B1 + BCH)          // 212480 (104 f32)
#define OFF_OW  (OFF_CB + NP * 4)       // 212896 (104 f32)
#define OFF_EP  (OFF_OW + NP * 4)       // 213312 (3*128 f32)
#define OFF_EN  (OFF_EP + 384 * 4)      // 214848 (3*128 f32)
#define SMEM_TOTAL (OFF_EN + 384 * 4)   // 216384

// preconverted weights: [mat(2)][t(8)][k(208)][n(104)] fp16, pads zero
__device__ __align__(16) __half g_W16[2 * T_TYPES * KP * NP];

// ---------------- helpers ----------------
__device__ __forceinline__ uint32_t smem_u32(const void* p) {
    uint32_t a;
    asm("{ .reg .u64 t; cvta.to.shared.u64 t, %1; cvt.u32.u64 %0, t; }" : "=r"(a) : "l"(p));
    return a;
}
__device__ __forceinline__ void ldsm_x4(uint32_t* r, uint32_t a) {
    asm volatile("ldmatrix.sync.aligned.m8n8.x4.shared.b16 {%0,%1,%2,%3}, [%4];"
        : "=r"(r[0]), "=r"(r[1]), "=r"(r[2]), "=r"(r[3]) : "r"(a));
}
__device__ __forceinline__ void ldsm_x4t(uint32_t* r, uint32_t a) {
    asm volatile("ldmatrix.sync.aligned.m8n8.x4.trans.shared.b16 {%0,%1,%2,%3}, [%4];"
        : "=r"(r[0]), "=r"(r[1]), "=r"(r[2]), "=r"(r[3]) : "r"(a));
}
__device__ __forceinline__ void ldsm_x2t(uint32_t* r, uint32_t a) {
    asm volatile("ldmatrix.sync.aligned.m8n8.x2.trans.shared.b16 {%0,%1}, [%2];"
        : "=r"(r[0]), "=r"(r[1]) : "r"(a));
}
__device__ __forceinline__ void mma16816(float* c, const uint32_t* a, const uint32_t* b) {
    asm volatile("mma.sync.aligned.m16n8k16.row.col.f32.f16.f16.f32 "
        "{%0,%1,%2,%3}, {%4,%5,%6,%7}, {%8,%9}, {%0,%1,%2,%3};"
        : "+f"(c[0]), "+f"(c[1]), "+f"(c[2]), "+f"(c[3])
        : "r"(a[0]), "r"(a[1]), "r"(a[2]), "r"(a[3]), "r"(b[0]), "r"(b[1]));
}
__device__ __forceinline__ uint32_t pack_h2(float x, float y) {
    __half2 t = __floats2half2_rn(x, y);
    return *reinterpret_cast<uint32_t*>(&t);
}
#define CP_COMMIT() asm volatile("cp.async.commit_group;" ::: "memory")
#define CP_WAIT1()  asm volatile("cp.async.wait_group 1;" ::: "memory")
#define CP_WAIT0()  asm volatile("cp.async.wait_group 0;" ::: "memory")

// stage one K-chunk of weight matrix mt (0..7 = Ws(t), 8..15 = Wd(t)) via cp.async
__device__ __forceinline__ void stage_chunk(int mt, int chunk, uint32_t dst_s, int tid) {
    const char* src = reinterpret_cast<const char*>(g_W16)
                    + ((size_t)mt * KP + (size_t)chunk * 112) * NP * 2;
    const int bytes = chunk ? (96 * BROWB) : (112 * BROWB);
    for (int off = tid * 16; off < bytes; off += NTHREADS * 16)
        asm volatile("cp.async.ca.shared.global [%0], [%1], 16;"
                     :: "r"(dst_s + (uint32_t)off), "l"(src + off) : "memory");
}

// ---------------- prologue: weights -> fp16 [mat][t][k][n], zero-padded ----------------
__global__ void wconv_kernel(const float* __restrict__ srcW, const float* __restrict__ dstW) {
    int i = blockIdx.x * blockDim.x + threadIdx.x;
    const int TOT = 2 * T_TYPES * KP * NP;
    if (i >= TOT) return;
    int n   = i % NP;
    int k   = (i / NP) % KP;
    int t   = (i / (NP * KP)) % T_TYPES;
    int mat = i / (NP * KP * T_TYPES);
    float v = 0.0f;
    if (k < D_K && n < H_N) {
        const float* W = mat ? dstW : srcW;
        v = W[(size_t)t * D_K * H_N + (size_t)k * H_N + n];
    }
    g_W16[i] = __float2half_rn(v);
}

// ---------------- K-segment loops ----------------
// src phase: c[r][j] += A_src @ Ws-chunk
template <int NBLK, int NSTEPS>
__device__ __forceinline__ void kseg_src(
    uint32_t a0, uint32_t a1, int s0,
    uint32_t b0, uint32_t b1, uint32_t b2,
    float (&c)[2][5][4])
{
#pragma unroll
    for (int ls = 0; ls < NSTEPS; ls++) {
        const uint32_t ka = (uint32_t)(s0 + ls) * 32;
        const uint32_t kb = (uint32_t)ls * 16 * BROWB;
        uint32_t A0[4], A1[4];
        ldsm_x4(A0, a0 + ka);
        ldsm_x4(A1, a1 + ka);
        uint32_t B[10];
        ldsm_x4t(B + 0, b0 + kb);
        ldsm_x4t(B + 4, b1 + kb);
        if (NBLK == 5) ldsm_x2t(B + 8, b2 + kb);
#pragma unroll
        for (int j = 0; j < NBLK; j++) {
            mma16816(c[0][j], A0, B + 2 * j);
            mma16816(c[1][j], A1, B + 2 * j);
        }
    }
}

// dst phase: cP += A_pos @ Wd-chunk ; cN += A_neg @ Wd-chunk
template <int NBLK, int NSTEPS>
__device__ __forceinline__ void kseg_dst(
    uint32_t p0, uint32_t p1, uint32_t q0, uint32_t q1, int s0,
    uint32_t b0, uint32_t b1, uint32_t b2,
    float (&cP)[2][5][4], float (&cN)[2][5][4])
{
#pragma unroll
    for (int ls = 0; ls < NSTEPS; ls++) {
        const uint32_t ka = (uint32_t)(s0 + ls) * 32;
        const uint32_t kb = (uint32_t)ls * 16 * BROWB;
        uint32_t P0[4], P1[4], Q0[4], Q1[4];
        ldsm_x4(P0, p0 + ka);
        ldsm_x4(P1, p1 + ka);
        ldsm_x4(Q0, q0 + ka);
        ldsm_x4(Q1, q1 + ka);
        uint32_t B[10];
        ldsm_x4t(B + 0, b0 + kb);
        ldsm_x4t(B + 4, b1 + kb);
        if (NBLK == 5) ldsm_x2t(B + 8, b2 + kb);
#pragma unroll
        for (int j = 0; j < NBLK; j++) {
            mma16816(cP[0][j], P0, B + 2 * j);
            mma16816(cP[1][j], P1, B + 2 * j);
            mma16816(cN[0][j], Q0, B + 2 * j);
            mma16816(cN[1][j], Q1, B + 2 * j);
        }
    }
}

// ---------------- main fused kernel ----------------
__global__ __launch_bounds__(NTHREADS, 1)
void sthn_hmma_kernel(const float* __restrict__ h,
                      const float* __restrict__ src_b, const float* __restrict__ dst_b,
                      const float* __restrict__ out_W, const float* __restrict__ out_b,
                      const int*   __restrict__ poss,
                      float* __restrict__ out)
{
    extern __shared__ char smem[];
    const uint32_t sb = smem_u32(smem);
    const int tid  = threadIdx.x;
    const int lane = tid & 31;
    const int w    = tid >> 5;
    const int n0   = blockIdx.x * P_PAIRS;

    // prologue: kick off Ws(0) chunk0/chunk1 while we convert A tiles
    stage_chunk(0, 0, sb + OFF_B0, tid); CP_COMMIT();
    stage_chunk(0, 1, sb + OFF_B1, tid); CP_COMMIT();

    // ---- convert the three A tiles fp32 -> fp16 into smem (once) ----
    {
        const int QUADS = KP / 4;   // 52 uint2-stores per row
        for (int idx = tid; idx < 3 * P_PAIRS * QUADS; idx += NTHREADS) {
            int tile = idx / (P_PAIRS * QUADS);
            int rem  = idx - tile * (P_PAIRS * QUADS);
            int row  = rem / QUADS;
            int k    = (rem - row * QUADS) * 4;
            uint2 v16;
            if (k < D_K) {
                const float4 v = *reinterpret_cast<const float4*>(
                    h + (size_t)(tile * E_EDGES + n0 + row) * D_K + k);
                v16.x = pack_h2(v.x, v.y);
                v16.y = pack_h2(v.z, v.w);
            } else { v16.x = 0u; v16.y = 0u; }
            *reinterpret_cast<uint2*>(smem + tile * A_SZ + row * AROWB + k * 2) = v16;
        }
    }

    // ---- per-warp fragment addressing ----
    const int mw = w & 3;               // M-warp: 32 rows
    const int ng = w >> 2;              // N-group 0..2
    const int mb = mw * 32;
    const int nbase = (ng == 0) ? 0 : (ng == 1 ? 5 : 9);
    const int nblk  = (ng == 0) ? 5 : 4;

    const uint32_t aOff0 = (uint32_t)(mb + (lane & 15)) * AROWB + (uint32_t)(lane >> 4) * 16;
    const uint32_t aOff1 = aOff0 + 16u * AROWB;
    const uint32_t aS0 = sb + OFF_AS + aOff0, aS1 = sb + OFF_AS + aOff1;
    const uint32_t aP0 = sb + OFF_AP + aOff0, aP1 = sb + OFF_AP + aOff1;
    const uint32_t aN0 = sb + OFF_AN + aOff0, aN1 = sb + OFF_AN + aOff1;

    const uint32_t bRow = (uint32_t)(lane & 15) * BROWB;
    const uint32_t bSel = (uint32_t)(lane >> 4);
    const uint32_t rb0 = bRow + (uint32_t)(nbase + 0 + bSel) * 16;
    const uint32_t rb1 = bRow + (uint32_t)(nbase + 2 + bSel) * 16;
    const uint32_t rb2 = bRow + (uint32_t)(nbase + 4) * 16;     // x2t block (ng0 only)
    const uint32_t bufb0 = sb + OFF_B0;
    const uint32_t bufb1 = sb + OFF_B1;

    float* EP = reinterpret_cast<float*>(smem + OFF_EP);
    float* EN = reinterpret_cast<float*>(smem + OFF_EN);
    const float* CB = reinterpret_cast<const float*>(smem + OFF_CB);
    const float* OW = reinterpret_cast<const float*>(smem + OFF_OW);

    float bestP = -1e30f, bestN = -1e30f;
    int   anyP = 0, anyN = 0;

    __syncthreads();   // A tiles complete

    for (int t = 0; t < T_TYPES; t++) {
        const int tn = (t + 1) & 7;
        float cP[2][5][4], cN[2][5][4];

        // ======== seg A: src GEMM on Ws chunk0 (buf0) ========
        CP_WAIT1();
        __syncthreads();
        if (tid < NP) {   // stage epilogue constants for this t
            int c = tid;
            float cb = 0.0f, ow = 0.0f;
            if (c < H_N) {
                cb = src_b[t * H_N + c] + dst_b[t * H_N + c];
                ow = out_W[t * H_N + c];
            }
            reinterpret_cast<float*>(smem + OFF_CB)[c] = cb;
            reinterpret_cast<float*>(smem + OFF_OW)[c] = ow;
        }
#pragma unroll
        for (int r = 0; r < 2; r++)
#pragma unroll
            for (int j = 0; j < 5; j++)
#pragma unroll
                for (int q = 0; q < 4; q++) cP[r][j][q] = 0.f;

        if (ng == 0) kseg_src<5,7>(aS0, aS1, 0, bufb0+rb0, bufb0+rb1, bufb0+rb2, cP);
        else         kseg_src<4,7>(aS0, aS1, 0, bufb0+rb0, bufb0+rb1, bufb0+rb2, cP);
        __syncthreads();
        stage_chunk(8 + t, 0, bufb0, tid); CP_COMMIT();   // Wd(t) chunk0

        // ======== seg B: src GEMM on Ws chunk1 (buf1) ========
        CP_WAIT1();
        __syncthreads();
        if (ng == 0) kseg_src<5,6>(aS0, aS1, 7, bufb1+rb0, bufb1+rb1, bufb1+rb2, cP);
        else         kseg_src<4,6>(aS0, aS1, 7, bufb1+rb0, bufb1+rb1, bufb1+rb2, cP);
        // src contribution is shared by pos and neg
#pragma unroll
        for (int r = 0; r < 2; r++)
#pragma unroll
            for (int j = 0; j < 5; j++)
#pragma unroll
                for (int q = 0; q < 4; q++) cN[r][j][q] = cP[r][j][q];
        __syncthreads();
        stage_chunk(8 + t, 1, bufb1, tid); CP_COMMIT();   // Wd(t) chunk1

        // ======== seg C: dst GEMMs on Wd chunk0 (buf0) ========
        CP_WAIT1();
        __syncthreads();
        if (ng == 0) kseg_dst<5,7>(aP0, aP1, aN0, aN1, 0, bufb0+rb0, bufb0+rb1, bufb0+rb2, cP, cN);
        else         kseg_dst<4,7>(aP0, aP1, aN0, aN1, 0, bufb0+rb0, bufb0+rb1, bufb0+rb2, cP, cN);
        __syncthreads();
        stage_chunk(tn, 0, bufb0, tid); CP_COMMIT();      // Ws(t+1) chunk0

        // ======== seg D: dst GEMMs on Wd chunk1 (buf1) ========
        CP_WAIT1();
        __syncthreads();
        if (ng == 0) kseg_dst<5,6>(aP0, aP1, aN0, aN1, 7, bufb1+rb0, bufb1+rb1, bufb1+rb2, cP, cN);
        else         kseg_dst<4,6>(aP0, aP1, aN0, aN1, 7, bufb1+rb0, bufb1+rb1, bufb1+rb2, cP, cN);
        __syncthreads();
        stage_chunk(tn, 1, bufb1, tid); CP_COMMIT();      // Ws(t+1) chunk1

        // ======== epilogue: relu + out_W dot, quad-reduce, masked max ========
#pragma unroll
        for (int r = 0; r < 2; r++) {
            float pP0 = 0.f, pP1 = 0.f, pN0 = 0.f, pN1 = 0.f;
            for (int j = 0; j < nblk; j++) {
                const int c0 = (nbase + j) * 8 + (lane & 3) * 2;
                const float cb0 = CB[c0], cb1 = CB[c0 + 1];
                const float ow0 = OW[c0], ow1 = OW[c0 + 1];
                pP0 += fmaxf(cP[r][j][0] + cb0, 0.f) * ow0 + fmaxf(cP[r][j][1] + cb1, 0.f) * ow1;
                pP1 += fmaxf(cP[r][j][2] + cb0, 0.f) * ow0 + fmaxf(cP[r][j][3] + cb1, 0.f) * ow1;
                pN0 += fmaxf(cN[r][j][0] + cb0, 0.f) * ow0 + fmaxf(cN[r][j][1] + cb1, 0.f) * ow1;
                pN1 += fmaxf(cN[r][j][2] + cb0, 0.f) * ow0 + fmaxf(cN[r][j][3] + cb1, 0.f) * ow1;
            }
#pragma unroll
            for (int off = 1; off <= 2; off <<= 1) {
                pP0 += __shfl_xor_sync(0xffffffffu, pP0, off);
                pP1 += __shfl_xor_sync(0xffffffffu, pP1, off);
                pN0 += __shfl_xor_sync(0xffffffffu, pN0, off);
                pN1 += __shfl_xor_sync(0xffffffffu, pN1, off);
            }
            if ((lane & 3) == 0) {
                const int r0 = mb + 16 * r + (lane >> 2);
                EP[ng * P_PAIRS + r0] = pP0;  EP[ng * P_PAIRS + r0 + 8] = pP1;
                EN[ng * P_PAIRS + r0] = pN0;  EN[ng * P_PAIRS + r0 + 8] = pN1;
            }
        }
        __syncthreads();

        if (tid < P_PAIRS) {
            const float ob = out_b[t];
            const float sp = EP[tid] + EP[P_PAIRS + tid] + EP[2 * P_PAIRS + tid] + ob;
            const float sn = EN[tid] + EN[P_PAIRS + tid] + EN[2 * P_PAIRS + tid] + ob;
            if (poss[(size_t)(n0 + tid) * T_TYPES + t] != 0)           { bestP = fmaxf(bestP, sp); anyP = 1; }
            if (poss[(size_t)(E_EDGES + n0 + tid) * T_TYPES + t] != 0) { bestN = fmaxf(bestN, sn); anyN = 1; }
        }
        __syncthreads();   // EP/EN reused next t
    }

    CP_WAIT0();   // drain the (harmless) trailing prefetches before exit

    if (tid < P_PAIRS) {
        out[n0 + tid]           = anyP ? bestP : 0.0f;
        out[E_EDGES + n0 + tid] = anyN ? bestN : 0.0f;
    }
}

// ---------------- launch ----------------
extern "C" void kernel_launch(void* const* d_in, const int* in_sizes, int n_in,
                              void* d_out, int out_size)
{
    const float* h      = (const float*)d_in[0];
    const float* src_W  = (const float*)d_in[1];
    const float* src_b  = (const float*)d_in[2];
    const float* dst_W  = (const float*)d_in[3];
    const float* dst_b  = (const float*)d_in[4];
    const float* out_W  = (const float*)d_in[5];
    const float* out_b  = (const float*)d_in[6];
    const int*   poss   = (const int*)d_in[7];
    float*       out    = (float*)d_out;

    cudaFuncSetAttribute(sthn_hmma_kernel,
                         cudaFuncAttributeMaxDynamicSharedMemorySize, SMEM_TOTAL);

    const int wtot = 2 * T_TYPES * KP * NP;
    wconv_kernel<<<(wtot + 255) / 256, 256>>>(src_W, dst_W);
    sthn_hmma_kernel<<<NCTA, NTHREADS, SMEM_TOTAL>>>(h, src_b, dst_b, out_W, out_b, poss, out);
}